// round 15
// baseline (speedup 1.0000x reference)
#include <cuda_runtime.h>
#include <cuda_fp16.h>
#include <cstdint>

// Problem constants
#define B_    256
#define S_    64
#define DIN_  1024
#define H_    512
#define H3_   1536
#define E_    512
#define M_    (S_ * B_)   // 16384 rows (t*B + b)

// Scratch (device globals; no runtime allocation allowed)
__device__ __half g_Xh[(size_t)M_ * DIN_];        // fp16 inputs for GEMM
__device__ __half g_Wih_h[2][(size_t)H3_ * DIN_]; // fp16 weights
__device__ __half g_Wproj_h[(size_t)E_ * 2 * H_];
__device__ float  g_GI[2][(size_t)M_ * H3_];      // input-transform, fp32
__device__ __half g_Hh[2][(size_t)M_ * H_];       // fp16 GRU outputs (GEMM + proj input)

// Group barriers: 8 objects (dir x batch-quarter), 32 arrivals each. Padded.
__device__ volatile unsigned g_bar_cnt[8 * 32];
__device__ volatile unsigned g_bar_gen[8 * 32];

// ---------------- low-level helpers ----------------
__device__ __forceinline__ void cp16s(uint32_t s, const void* g) {
    asm volatile("cp.async.cg.shared.global [%0], [%1], 16;\n" :: "r"(s), "l"(g));
}
__device__ __forceinline__ void cp_commit() {
    asm volatile("cp.async.commit_group;\n" ::);
}
template <int N> __device__ __forceinline__ void cp_wait() {
    asm volatile("cp.async.wait_group %0;\n" :: "n"(N));
}

__device__ __forceinline__ uint2 f4h(float4 v) {
    __half2 a = __floats2half2_rn(v.x, v.y);
    __half2 b = __floats2half2_rn(v.z, v.w);
    uint2 r;
    r.x = *reinterpret_cast<uint32_t*>(&a);
    r.y = *reinterpret_cast<uint32_t*>(&b);
    return r;
}

__device__ __forceinline__ float tanhax(float x) {
    float y;
    asm("tanh.approx.f32 %0, %1;" : "=f"(y) : "f"(x));
    return y;
}

__device__ __forceinline__ void ldsm4(uint32_t& r0, uint32_t& r1, uint32_t& r2,
                                      uint32_t& r3, uint32_t addr) {
    asm volatile("ldmatrix.sync.aligned.m8n8.x4.shared.b16 {%0,%1,%2,%3}, [%4];"
                 : "=r"(r0), "=r"(r1), "=r"(r2), "=r"(r3) : "r"(addr));
}

// fp16 MMA, fp32 accumulate: D[16x8] += A[16x16] * B[16x8]
__device__ __forceinline__ void mma16(float* d, const uint32_t* a,
                                      uint32_t b0, uint32_t b1) {
    asm volatile(
        "mma.sync.aligned.m16n8k16.row.col.f32.f16.f16.f32 "
        "{%0,%1,%2,%3},{%4,%5,%6,%7},{%8,%9},{%0,%1,%2,%3};"
        : "+f"(d[0]), "+f"(d[1]), "+f"(d[2]), "+f"(d[3])
        : "r"(a[0]), "r"(a[1]), "r"(a[2]), "r"(a[3]), "r"(b0), "r"(b1));
}

// ---------------------------------------------------------------------------
// Kernel 0: convert weights to fp16 scratch
// ---------------------------------------------------------------------------
__global__ void round_weights_kernel(const float4* __restrict__ wf,
                                     const float4* __restrict__ wb,
                                     const float4* __restrict__ wp) {
    const int NW = H3_ * DIN_ / 4;   // 393216
    const int NP = E_ * 2 * H_ / 4;  // 131072
    int i = blockIdx.x * blockDim.x + threadIdx.x;
    if (i < NW) {
        ((uint2*)g_Wih_h[0])[i] = f4h(wf[i]);
        ((uint2*)g_Wih_h[1])[i] = f4h(wb[i]);
        if (i < NP) ((uint2*)g_Wproj_h)[i] = f4h(wp[i]);
    }
}

// ---------------------------------------------------------------------------
// Kernel 1: gather slot embedding + concat value embeds -> Xh (fp16)
// ---------------------------------------------------------------------------
__global__ void build_x_kernel(const int* __restrict__ slot_ids,
                               const float* __restrict__ value_embeds,
                               const float* __restrict__ embed_table) {
    int m = blockIdx.x;            // = t*B + b
    int t = m >> 8;
    int b = m & 255;
    int c4 = threadIdx.x;          // float4 column 0..255
    float4 v;
    if (c4 < 64) {
        int sid = slot_ids[b * S_ + t];
        v = ((const float4*)embed_table)[(size_t)sid * 64 + c4];
    } else {
        v = ((const float4*)value_embeds)[(size_t)(b * S_ + t) * 192 + (c4 - 64)];
    }
    ((uint2*)g_Xh)[(size_t)m * 256 + c4] = f4h(v);
}

// ---------------------------------------------------------------------------
// Kernel 2/4: fp16 mma.sync GEMM, 512 threads (16 warps = 4M x 4N),
// warp tile 32x64, K-chunk 64 halfs (128B SW128 rows), 3-stage cp.async.
// (unchanged from round 13)
// ---------------------------------------------------------------------------
#define GSMEM_BYTES 147456

template <bool PROJ>
__global__ __launch_bounds__(512, 1)
void mm_gemm_kernel(float* __restrict__ outp) {
    extern __shared__ __align__(128) char smc[];
    const uint32_t sbase = (uint32_t)__cvta_generic_to_shared(smc);
    const int tid  = threadIdx.x;
    const int lane = tid & 31;
    const int warp = tid >> 5;          // 0..15
    const int n0  = blockIdx.x * 256;
    const int m0  = blockIdx.y * 128;
    const int dir = blockIdx.z;

    const __half* __restrict__ Wg = PROJ ? g_Wproj_h : g_Wih_h[dir];

    const int wm = (warp & 3) * 32;
    const int wn = (warp >> 2) * 64;

    const int a_rr = lane & 15;
    const int a_cs = lane >> 4;
    const int b_rr = (lane & 7) | ((lane & 16) >> 1);
    const int b_cs = (lane >> 3) & 1;

    float acc[2][8][4];
    #pragma unroll
    for (int i = 0; i < 2; i++)
        #pragma unroll
        for (int j = 0; j < 8; j++)
            #pragma unroll
            for (int e = 0; e < 4; e++) acc[i][j][e] = 0.0f;

    auto stage = [&](int s, int kt) {
        #pragma unroll
        for (int q = 0; q < 2; q++) {            // A: 1024 cp16
            int id = tid + q * 512;
            int r = id >> 3, c8 = id & 7;
            const __half* src;
            if (PROJ) {
                const __half* hs = (kt < 8) ? g_Hh[0] : g_Hh[1];
                src = &hs[(size_t)(m0 + r) * H_ + (kt & 7) * 64 + c8 * 8];
            } else {
                src = &g_Xh[(size_t)(m0 + r) * DIN_ + kt * 64 + c8 * 8];
            }
            cp16s(sbase + s * 16384 + r * 128 + ((c8 ^ (r & 7)) << 4), src);
        }
        #pragma unroll
        for (int q = 0; q < 4; q++) {            // B: 2048 cp16
            int id = tid + q * 512;
            int r = id >> 3, c8 = id & 7;
            cp16s(sbase + 49152 + s * 32768 + r * 128 + ((c8 ^ (r & 7)) << 4),
                  &Wg[(size_t)(n0 + r) * 1024 + kt * 64 + c8 * 8]);
        }
    };

    stage(0, 0); cp_commit();
    stage(1, 1); cp_commit();

    for (int kt = 0; kt < 16; kt++) {
        if (kt < 15) cp_wait<1>(); else cp_wait<0>();
        __syncthreads();
        if (kt + 2 < 16) { stage((kt + 2) % 3, kt + 2); cp_commit(); }

        const int s = kt % 3;
        const uint32_t sa = sbase + s * 16384;
        const uint32_t sb = sbase + 49152 + s * 32768;

        #pragma unroll
        for (int k16 = 0; k16 < 4; k16++) {
            uint32_t a[2][4];
            #pragma unroll
            for (int mi = 0; mi < 2; mi++) {
                int rr = wm + 16 * mi + a_rr;
                ldsm4(a[mi][0], a[mi][1], a[mi][2], a[mi][3],
                      sa + rr * 128 + (((2 * k16 + a_cs) ^ (rr & 7)) << 4));
            }
            #pragma unroll
            for (int g2 = 0; g2 < 4; g2++) {
                int rr = wn + 16 * g2 + b_rr;
                uint32_t b0, b1, b2, b3;
                ldsm4(b0, b1, b2, b3,
                      sb + rr * 128 + (((2 * k16 + b_cs) ^ (rr & 7)) << 4));
                #pragma unroll
                for (int mi = 0; mi < 2; mi++) {
                    mma16(acc[mi][2 * g2], a[mi], b0, b1);
                    mma16(acc[mi][2 * g2 + 1], a[mi], b2, b3);
                }
            }
        }
    }

    const int re = lane >> 2, ce = 2 * (lane & 3);
    #pragma unroll
    for (int mi = 0; mi < 2; mi++) {
        #pragma unroll
        for (int j = 0; j < 8; j++) {
            int row = m0 + wm + 16 * mi + re;
            int col = n0 + wn + 8 * j + ce;
            if (!PROJ) {
                float* C = g_GI[dir];
                *(float2*)&C[(size_t)row * H3_ + col] =
                    make_float2(acc[mi][j][0], acc[mi][j][1]);
                *(float2*)&C[(size_t)(row + 8) * H3_ + col] =
                    make_float2(acc[mi][j][2], acc[mi][j][3]);
            } else {
                int r1 = row, r2 = row + 8;
                size_t o1 = ((size_t)(r1 & 255) * S_ + (r1 >> 8)) * E_ + col;
                size_t o2 = ((size_t)(r2 & 255) * S_ + (r2 >> 8)) * E_ + col;
                *(float2*)&outp[o1] = make_float2(acc[mi][j][0], acc[mi][j][1]);
                *(float2*)&outp[o2] = make_float2(acc[mi][j][2], acc[mi][j][3]);
            }
        }
    }
}

// ---------------------------------------------------------------------------
// Kernel 3: PERSISTENT bidirectional GRU, DIR-INTERLEAVED.
// 128 CTAs x 512 threads. cta -> j-slice (32 x 16 cols) x batch-quarter (4 x 64).
// Each CTA processes BOTH directions; the inter-CTA barrier wait of one
// direction is hidden under the other direction's GEMM+epilogue.
// Warps: 16 = 4 M-slices (16 rows) x 4 K-quarters (128 cols); GH holds 4
// partials reduced in the epilogue. h fp32 trajectory in registers.
// SMEM: WSM [2d][8kc][48][128B] = 96KB @0 | ASM [8kc][64][128B] = 64KB @98304
//       GH [4kq][64][48] fp32 = 48KB @163840.  Total 212992 B.
// ---------------------------------------------------------------------------
#define WSM_OFF 0
#define ASM_OFF 98304
#define GH_OFF  163840
#define PSMEM_BYTES 212992

__global__ __launch_bounds__(512, 1)
void gru_persistent_kernel(const float* __restrict__ Whh_f,
                           const float* __restrict__ Whh_b,
                           const float* __restrict__ bih_f,
                           const float* __restrict__ bhh_f,
                           const float* __restrict__ bih_b,
                           const float* __restrict__ bhh_b) {
    extern __shared__ __align__(128) char smc[];
    const uint32_t sbase = (uint32_t)__cvta_generic_to_shared(smc);
    float* GH = (float*)(smc + GH_OFF);

    const int cta = blockIdx.x;
    const int j0  = (cta >> 2) * 16;
    const int bq  = cta & 3;
    const int b0  = bq * 64;

    const int tid  = threadIdx.x;
    const int lane = tid & 31;
    const int warp = tid >> 5;         // 0..15
    const int ms   = warp & 3;         // M-slice (16 rows)
    const int kq   = warp >> 2;        // K-quarter (128 cols)

    const int a_rr = lane & 15;
    const int a_cs = lane >> 4;
    const int b_rr = (lane & 7) | ((lane & 16) >> 1);
    const int b_cs = (lane >> 3) & 1;

    const int jc = j0 + (tid & 15);
    const int r0 = tid >> 4;           // 0..31; epilogue rows r0, r0+32

    // Biases for both dirs
    float bias_r[2], bias_z[2], bias_in[2], bias_hn[2];
    bias_r[0]  = bih_f[jc] + bhh_f[jc];
    bias_z[0]  = bih_f[H_ + jc] + bhh_f[H_ + jc];
    bias_in[0] = bih_f[2 * H_ + jc];
    bias_hn[0] = bhh_f[2 * H_ + jc];
    bias_r[1]  = bih_b[jc] + bhh_b[jc];
    bias_z[1]  = bih_b[H_ + jc] + bhh_b[H_ + jc];
    bias_in[1] = bih_b[2 * H_ + jc];
    bias_hn[1] = bhh_b[2 * H_ + jc];

    // Load Whh slices for BOTH dirs: [d][kc][48 rows][128B], SW128.
    #pragma unroll
    for (int d = 0; d < 2; d++) {
        const float* __restrict__ Whh = d ? Whh_b : Whh_f;
        for (int idx = tid; idx < 48 * 64; idx += 512) {
            int row = idx >> 6;          // 0..47 (= gate*16 + jl)
            int c   = idx & 63;          // 8-half chunk index
            int kc = c >> 3, c8 = c & 7;
            int g = row >> 4, jl = row & 15;
            const float4* src = (const float4*)
                &Whh[((size_t)(g * H_ + j0 + jl)) * H_ + c * 8];
            uint2 lo = f4h(src[0]);
            uint2 hi = f4h(src[1]);
            uint4 w = make_uint4(lo.x, lo.y, hi.x, hi.y);
            *(uint4*)(smc + WSM_OFF + d * 49152 + kc * 6144 + row * 128
                      + ((c8 ^ (row & 7)) << 4)) = w;
        }
    }
    __syncthreads();

    // ---- helpers ----
    auto stageA = [&](int d, int row_prev) {   // 64 rows x 512 halfs
        const __half* __restrict__ hh = &g_Hh[d][(size_t)row_prev * B_ * H_];
        #pragma unroll
        for (int q = 0; q < 8; q++) {
            int id = tid + q * 512;        // 0..4095
            int kc = id >> 9;
            int r = (id >> 3) & 63, c8 = id & 7;
            cp16s(sbase + ASM_OFF + kc * 8192 + r * 128 + ((c8 ^ (r & 7)) << 4),
                  &hh[(size_t)(b0 + r) * H_ + kc * 64 + c8 * 8]);
        }
        cp_commit();
    };

    auto gemm = [&](int d) {                  // -> GH partials
        float acc[6][4];
        #pragma unroll
        for (int j = 0; j < 6; j++)
            #pragma unroll
            for (int e = 0; e < 4; e++) acc[j][e] = 0.0f;
        #pragma unroll
        for (int i = 0; i < 2; i++) {
            const int kc = kq * 2 + i;
            const uint32_t sa = sbase + ASM_OFF + kc * 8192;
            const uint32_t wb = sbase + WSM_OFF + d * 49152 + kc * 6144;
            #pragma unroll
            for (int k16 = 0; k16 < 4; k16++) {
                uint32_t a[4];
                int rr = ms * 16 + a_rr;
                ldsm4(a[0], a[1], a[2], a[3],
                      sa + rr * 128 + (((2 * k16 + a_cs) ^ (rr & 7)) << 4));
                #pragma unroll
                for (int g2 = 0; g2 < 3; g2++) {
                    int br = g2 * 16 + b_rr;
                    uint32_t bb0, bb1, bb2, bb3;
                    ldsm4(bb0, bb1, bb2, bb3,
                          wb + br * 128 + (((2 * k16 + b_cs) ^ (br & 7)) << 4));
                    mma16(acc[2 * g2], a, bb0, bb1);
                    mma16(acc[2 * g2 + 1], a, bb2, bb3);
                }
            }
        }
        const int re = lane >> 2, ce = 2 * (lane & 3);
        #pragma unroll
        for (int j = 0; j < 6; j++) {
            int row = ms * 16 + re;
            int col = 8 * j + ce;
            int off = (kq * 64 + row) * 48 + col;
            *(float2*)&GH[off] = make_float2(acc[j][0], acc[j][1]);
            *(float2*)&GH[off + 8 * 48] = make_float2(acc[j][2], acc[j][3]);
        }
    };

    // Barrier arrive / wait (tid-0 gen snapshot kept in registers)
    unsigned gsnap[2];
    auto arrive = [&](int d) {
        __syncthreads();                       // all STG issued
        if (tid == 0) {
            int grp = (d * 4 + bq) * 32;
            __threadfence();
            gsnap[d] = g_bar_gen[grp];
            unsigned a = atomicAdd((unsigned*)&g_bar_cnt[grp], 1u);
            if (a == 31) {
                g_bar_cnt[grp] = 0;
                __threadfence();
                atomicAdd((unsigned*)&g_bar_gen[grp], 1u);
            }
        }
    };
    auto wait = [&](int d) {
        if (tid == 0) {
            int grp = (d * 4 + bq) * 32;
            while (g_bar_gen[grp] == gsnap[d]) { }
            __threadfence();
        }
        __syncthreads();
    };

    // GI prefetch (per dir, row rs) into caller-provided regs
    float pf_r[2][2], pf_z[2][2], pf_n[2][2];
    auto prefGI = [&](int d, int rs) {
        const float* __restrict__ GId = g_GI[d];
        const size_t gi_base = (size_t)(rs * B_) * H3_;
        #pragma unroll
        for (int k = 0; k < 2; k++) {
            size_t girow = gi_base + (size_t)(b0 + r0 + 32 * k) * H3_;
            pf_r[d][k] = GId[girow + jc];
            pf_z[d][k] = GId[girow + H_ + jc];
            pf_n[d][k] = GId[girow + 2 * H_ + jc];
        }
    };

    float php[2][2] = {{0.f, 0.f}, {0.f, 0.f}};   // fp32 h in registers

    auto epilogue = [&](int d, int tau, int row_store) {
        __half* __restrict__ Hd = g_Hh[d];
        const size_t h_base = (size_t)(row_store * B_) * H_;
        const int c = tid & 15;
        #pragma unroll
        for (int k = 0; k < 2; k++) {
            int r = r0 + 32 * k;
            float hr_ = 0.f, hz = 0.f, hn = 0.f;
            if (tau > 0) {
                #pragma unroll
                for (int q = 0; q < 4; q++) {
                    int off = (q * 64 + r) * 48 + c;
                    hr_ += GH[off];
                    hz  += GH[off + 16];
                    hn  += GH[off + 32];
                }
            }
            float rg = 0.5f + 0.5f * tanhax(0.5f * (pf_r[d][k] + hr_ + bias_r[d]));
            float zg = 0.5f + 0.5f * tanhax(0.5f * (pf_z[d][k] + hz + bias_z[d]));
            float ng = tanhax(pf_n[d][k] + bias_in[d] + rg * (hn + bias_hn[d]));
            float hnew = fmaf(zg, php[d][k] - ng, ng);
            php[d][k] = hnew;
            Hd[h_base + (size_t)(b0 + r) * H_ + jc] = __float2half_rn(hnew);
        }
    };

    // ---- tau = 0: epilogue only (h = 0), both dirs ----
    prefGI(0, 0);
    prefGI(1, S_ - 1);
    epilogue(0, 0, 0);
    arrive(0);
    epilogue(1, 0, S_ - 1);
    arrive(1);
    prefGI(0, 1);
    prefGI(1, S_ - 2);
    wait(0);
    stageA(0, 0);          // h_f(0) lives at row 0

    for (int tau = 1; tau < S_; tau++) {
        // ---- dir f ----
        cp_wait<0>();
        __syncthreads();                 // A_f ready
        gemm(0);
        __syncthreads();                 // GH written -> readable
        epilogue(0, tau, tau);
        arrive(0);                       // includes syncthreads (ASM reads done)

        // ---- dir b (its barrier arrived ~one phase ago -> wait cheap) ----
        wait(1);
        stageA(1, S_ - tau);             // h_b(tau-1) stored at row S-tau
        cp_wait<0>();
        __syncthreads();
        gemm(1);
        __syncthreads();
        epilogue(1, tau, S_ - 1 - tau);
        arrive(1);

        if (tau < S_ - 1) {
            prefGI(0, tau + 1);
            prefGI(1, S_ - 2 - tau);
            wait(0);
            stageA(0, tau);              // h_f(tau) at row tau
        }
    }
}

// ---------------------------------------------------------------------------
extern "C" void kernel_launch(void* const* d_in, const int* in_sizes, int n_in,
                              void* d_out, int out_size) {
    const int*   slot_ids = (const int*)d_in[0];
    const float* value    = (const float*)d_in[1];
    const float* table    = (const float*)d_in[2];
    const float* Wih_f    = (const float*)d_in[3];
    const float* Whh_f    = (const float*)d_in[4];
    const float* bih_f    = (const float*)d_in[5];
    const float* bhh_f    = (const float*)d_in[6];
    const float* Wih_b    = (const float*)d_in[7];
    const float* Whh_b    = (const float*)d_in[8];
    const float* bih_b    = (const float*)d_in[9];
    const float* bhh_b    = (const float*)d_in[10];
    const float* Wproj    = (const float*)d_in[11];
    float* out = (float*)d_out;

    cudaFuncSetAttribute(mm_gemm_kernel<false>,
                         cudaFuncAttributeMaxDynamicSharedMemorySize, GSMEM_BYTES);
    cudaFuncSetAttribute(mm_gemm_kernel<true>,
                         cudaFuncAttributeMaxDynamicSharedMemorySize, GSMEM_BYTES);
    cudaFuncSetAttribute(gru_persistent_kernel,
                         cudaFuncAttributeMaxDynamicSharedMemorySize, PSMEM_BYTES);

    round_weights_kernel<<<(H3_ * DIN_ / 4 + 255) / 256, 256>>>(
        (const float4*)Wih_f, (const float4*)Wih_b, (const float4*)Wproj);
    build_x_kernel<<<M_, 256>>>(slot_ids, value, table);
    mm_gemm_kernel<false><<<dim3(H3_ / 256, M_ / 128, 2), 512, GSMEM_BYTES>>>(nullptr);
    gru_persistent_kernel<<<128, 512, PSMEM_BYTES>>>(
        Whh_f, Whh_b, bih_f, bhh_f, bih_b, bhh_b);
    mm_gemm_kernel<true><<<dim3(E_ / 256, M_ / 128, 1), 512, GSMEM_BYTES>>>(out);
}

// round 16
// speedup vs baseline: 1.2996x; 1.2996x over previous
#include <cuda_runtime.h>
#include <cuda_fp16.h>
#include <cstdint>

// Problem constants
#define B_    256
#define S_    64
#define DIN_  1024
#define H_    512
#define H3_   1536
#define E_    512
#define M_    (S_ * B_)   // 16384 rows (t*B + b)

// Scratch (device globals; no runtime allocation allowed)
__device__ __half g_Xh[(size_t)M_ * DIN_];        // fp16 inputs for GEMM
__device__ __half g_Wih_h[2][(size_t)H3_ * DIN_]; // fp16 weights
__device__ __half g_Wproj_h[(size_t)E_ * 2 * H_];
__device__ float  g_GI[2][(size_t)M_ * H3_];      // input-transform, fp32
__device__ __half g_Hh[2][(size_t)M_ * H_];       // fp16 GRU outputs (GEMM + proj input)

// Group barrier state: 4 groups (dir x b-half), 32 CTAs each. Padded lines.
__device__ volatile unsigned g_bar_cnt[4 * 32];
__device__ volatile unsigned g_bar_gen[4 * 32];

// ---------------- low-level helpers ----------------
__device__ __forceinline__ void cp16s(uint32_t s, const void* g) {
    asm volatile("cp.async.cg.shared.global [%0], [%1], 16;\n" :: "r"(s), "l"(g));
}
__device__ __forceinline__ void cp_commit() {
    asm volatile("cp.async.commit_group;\n" ::);
}
template <int N> __device__ __forceinline__ void cp_wait() {
    asm volatile("cp.async.wait_group %0;\n" :: "n"(N));
}

__device__ __forceinline__ uint2 f4h(float4 v) {
    __half2 a = __floats2half2_rn(v.x, v.y);
    __half2 b = __floats2half2_rn(v.z, v.w);
    uint2 r;
    r.x = *reinterpret_cast<uint32_t*>(&a);
    r.y = *reinterpret_cast<uint32_t*>(&b);
    return r;
}

__device__ __forceinline__ float tanhax(float x) {
    float y;
    asm("tanh.approx.f32 %0, %1;" : "=f"(y) : "f"(x));
    return y;
}

__device__ __forceinline__ void ldsm4(uint32_t& r0, uint32_t& r1, uint32_t& r2,
                                      uint32_t& r3, uint32_t addr) {
    asm volatile("ldmatrix.sync.aligned.m8n8.x4.shared.b16 {%0,%1,%2,%3}, [%4];"
                 : "=r"(r0), "=r"(r1), "=r"(r2), "=r"(r3) : "r"(addr));
}

// fp16 MMA, fp32 accumulate: D[16x8] += A[16x16] * B[16x8]
__device__ __forceinline__ void mma16(float* d, const uint32_t* a,
                                      uint32_t b0, uint32_t b1) {
    asm volatile(
        "mma.sync.aligned.m16n8k16.row.col.f32.f16.f16.f32 "
        "{%0,%1,%2,%3},{%4,%5,%6,%7},{%8,%9},{%0,%1,%2,%3};"
        : "+f"(d[0]), "+f"(d[1]), "+f"(d[2]), "+f"(d[3])
        : "r"(a[0]), "r"(a[1]), "r"(a[2]), "r"(a[3]), "r"(b0), "r"(b1));
}

// ---------------------------------------------------------------------------
// Kernel 0: convert weights to fp16 scratch
// ---------------------------------------------------------------------------
__global__ void round_weights_kernel(const float4* __restrict__ wf,
                                     const float4* __restrict__ wb,
                                     const float4* __restrict__ wp) {
    const int NW = H3_ * DIN_ / 4;   // 393216
    const int NP = E_ * 2 * H_ / 4;  // 131072
    int i = blockIdx.x * blockDim.x + threadIdx.x;
    if (i < NW) {
        ((uint2*)g_Wih_h[0])[i] = f4h(wf[i]);
        ((uint2*)g_Wih_h[1])[i] = f4h(wb[i]);
        if (i < NP) ((uint2*)g_Wproj_h)[i] = f4h(wp[i]);
    }
}

// ---------------------------------------------------------------------------
// Kernel 1: gather slot embedding + concat value embeds -> Xh (fp16)
// ---------------------------------------------------------------------------
__global__ void build_x_kernel(const int* __restrict__ slot_ids,
                               const float* __restrict__ value_embeds,
                               const float* __restrict__ embed_table) {
    int m = blockIdx.x;            // = t*B + b
    int t = m >> 8;
    int b = m & 255;
    int c4 = threadIdx.x;          // float4 column 0..255
    float4 v;
    if (c4 < 64) {
        int sid = slot_ids[b * S_ + t];
        v = ((const float4*)embed_table)[(size_t)sid * 64 + c4];
    } else {
        v = ((const float4*)value_embeds)[(size_t)(b * S_ + t) * 192 + (c4 - 64)];
    }
    ((uint2*)g_Xh)[(size_t)m * 256 + c4] = f4h(v);
}

// ---------------------------------------------------------------------------
// Kernel 2/4: fp16 mma.sync GEMM, 256 threads (8 warps = 4M x 2N),
// warp tile 32x64, CTA tile 128x128, K-chunk 64 halfs (128B SW128 rows),
// 3-stage cp.async, ONE sync per K-step, 2 CTAs/SM.
//   PROJ=false: GI[dir] = X @ Wih[dir]^T   (M=16384, N=1536, K=1024)
//   PROJ=true:  out = concat(Hf,Hb) @ Wproj^T, stored transposed to [B][S][E]
// SMEM: A[3][128][128B] @0 (48KB), B[3][128][128B] @49152 (48KB). Total 96KB.
// ---------------------------------------------------------------------------
#define GSMEM_BYTES 98304

template <bool PROJ>
__global__ __launch_bounds__(256, 2)
void mm_gemm_kernel(float* __restrict__ outp) {
    extern __shared__ __align__(128) char smc[];
    const uint32_t sbase = (uint32_t)__cvta_generic_to_shared(smc);
    const int tid  = threadIdx.x;
    const int lane = tid & 31;
    const int warp = tid >> 5;          // 0..7
    const int n0  = blockIdx.x * 128;
    const int m0  = blockIdx.y * 128;
    const int dir = blockIdx.z;

    const __half* __restrict__ Wg = PROJ ? g_Wproj_h : g_Wih_h[dir];

    const int wm = (warp & 3) * 32;
    const int wn = (warp >> 2) * 64;

    const int a_rr = lane & 15;
    const int a_cs = lane >> 4;
    const int b_rr = (lane & 7) | ((lane & 16) >> 1);
    const int b_cs = (lane >> 3) & 1;

    float acc[2][8][4];
    #pragma unroll
    for (int i = 0; i < 2; i++)
        #pragma unroll
        for (int j = 0; j < 8; j++)
            #pragma unroll
            for (int e = 0; e < 4; e++) acc[i][j][e] = 0.0f;

    auto stage = [&](int s, int kt) {
        #pragma unroll
        for (int q = 0; q < 4; q++) {            // A: 1024 cp16
            int id = tid + q * 256;
            int r = id >> 3, c8 = id & 7;
            const __half* src;
            if (PROJ) {
                const __half* hs = (kt < 8) ? g_Hh[0] : g_Hh[1];
                src = &hs[(size_t)(m0 + r) * H_ + (kt & 7) * 64 + c8 * 8];
            } else {
                src = &g_Xh[(size_t)(m0 + r) * DIN_ + kt * 64 + c8 * 8];
            }
            cp16s(sbase + s * 16384 + r * 128 + ((c8 ^ (r & 7)) << 4), src);
        }
        #pragma unroll
        for (int q = 0; q < 4; q++) {            // B: 1024 cp16
            int id = tid + q * 256;
            int r = id >> 3, c8 = id & 7;
            cp16s(sbase + 49152 + s * 16384 + r * 128 + ((c8 ^ (r & 7)) << 4),
                  &Wg[(size_t)(n0 + r) * 1024 + kt * 64 + c8 * 8]);
        }
    };

    stage(0, 0); cp_commit();
    stage(1, 1); cp_commit();

    for (int kt = 0; kt < 16; kt++) {
        if (kt < 15) cp_wait<1>(); else cp_wait<0>();
        __syncthreads();
        if (kt + 2 < 16) { stage((kt + 2) % 3, kt + 2); cp_commit(); }

        const int s = kt % 3;
        const uint32_t sa = sbase + s * 16384;
        const uint32_t sb = sbase + 49152 + s * 16384;

        #pragma unroll
        for (int k16 = 0; k16 < 4; k16++) {
            uint32_t a[2][4];
            #pragma unroll
            for (int mi = 0; mi < 2; mi++) {
                int rr = wm + 16 * mi + a_rr;
                ldsm4(a[mi][0], a[mi][1], a[mi][2], a[mi][3],
                      sa + rr * 128 + (((2 * k16 + a_cs) ^ (rr & 7)) << 4));
            }
            #pragma unroll
            for (int g2 = 0; g2 < 4; g2++) {
                int rr = wn + 16 * g2 + b_rr;
                uint32_t b0, b1, b2, b3;
                ldsm4(b0, b1, b2, b3,
                      sb + rr * 128 + (((2 * k16 + b_cs) ^ (rr & 7)) << 4));
                #pragma unroll
                for (int mi = 0; mi < 2; mi++) {
                    mma16(acc[mi][2 * g2], a[mi], b0, b1);
                    mma16(acc[mi][2 * g2 + 1], a[mi], b2, b3);
                }
            }
        }
    }

    const int re = lane >> 2, ce = 2 * (lane & 3);
    #pragma unroll
    for (int mi = 0; mi < 2; mi++) {
        #pragma unroll
        for (int j = 0; j < 8; j++) {
            int row = m0 + wm + 16 * mi + re;
            int col = n0 + wn + 8 * j + ce;
            if (!PROJ) {
                float* C = g_GI[dir];
                *(float2*)&C[(size_t)row * H3_ + col] =
                    make_float2(acc[mi][j][0], acc[mi][j][1]);
                *(float2*)&C[(size_t)(row + 8) * H3_ + col] =
                    make_float2(acc[mi][j][2], acc[mi][j][3]);
            } else {
                int r1 = row, r2 = row + 8;
                size_t o1 = ((size_t)(r1 & 255) * S_ + (r1 >> 8)) * E_ + col;
                size_t o2 = ((size_t)(r2 & 255) * S_ + (r2 >> 8)) * E_ + col;
                *(float2*)&outp[o1] = make_float2(acc[mi][j][0], acc[mi][j][1]);
                *(float2*)&outp[o2] = make_float2(acc[mi][j][2], acc[mi][j][3]);
            }
        }
    }
}

// ---------------------------------------------------------------------------
// Kernel 3: PERSISTENT bidirectional GRU recurrence, fp16 GEMM.
// (R13 champion version, verbatim.)
// 128 CTAs x 512 threads (16 warps = 8 M-slices x 2 K-halves).
// h fp32 trajectory lives ENTIRELY in registers (php[4] per thread).
// A tile (128x512 fp16 = 128KB) staged single-buffered in two commits
// interleaved across K-halves.
// SMEM: WSM [8kc][48][128B] = 48KB @0 | ASM [8kc][128][128B] = 128KB @49152.
// GH (fp32, 2x128x48 = 48KB) overlays ASM. Total 180224 B.
// ---------------------------------------------------------------------------
#define WSM_OFF 0
#define ASM_OFF 49152
#define GH_OFF  49152
#define PSMEM_BYTES (49152 + 131072)

__global__ __launch_bounds__(512, 1)
void gru_persistent_kernel(const float* __restrict__ Whh_f,
                           const float* __restrict__ Whh_b,
                           const float* __restrict__ bih_f,
                           const float* __restrict__ bhh_f,
                           const float* __restrict__ bih_b,
                           const float* __restrict__ bhh_b) {
    extern __shared__ __align__(128) char smc[];
    const uint32_t sbase = (uint32_t)__cvta_generic_to_shared(smc);
    float* GH = (float*)(smc + GH_OFF);

    const int cta = blockIdx.x;
    const int dir = cta >> 6;
    const int rem = cta & 63;
    const int j0  = (rem >> 1) * 16;
    const int b0  = (rem & 1) * 128;
    const int grp = (dir << 1) | (rem & 1);
    volatile unsigned* bar_cnt = &g_bar_cnt[grp * 32];
    volatile unsigned* bar_gen = &g_bar_gen[grp * 32];

    const int tid  = threadIdx.x;
    const int lane = tid & 31;
    const int warp = tid >> 5;         // 0..15
    const int kh   = warp >> 3;        // K-half 0/1
    const int wm16 = (warp & 7) * 16;  // 16-row M slice

    const int a_rr = lane & 15;
    const int a_cs = lane >> 4;
    const int b_rr = (lane & 7) | ((lane & 16) >> 1);
    const int b_cs = (lane >> 3) & 1;

    const float* __restrict__ Whh = dir ? Whh_b : Whh_f;
    const float* __restrict__ bih = dir ? bih_b : bih_f;
    const float* __restrict__ bhh = dir ? bhh_b : bhh_f;
    float*  __restrict__ GI  = g_GI[dir];
    __half* __restrict__ Hhd = g_Hh[dir];

    const int jc = j0 + (tid & 15);
    const int rbase = tid >> 4;        // 0..31; epilogue rows rbase + 32*k
    const float bias_r  = bih[jc]           + bhh[jc];
    const float bias_z  = bih[H_ + jc]      + bhh[H_ + jc];
    const float bias_in = bih[2 * H_ + jc];
    const float bias_hn = bhh[2 * H_ + jc];

    // Load Whh slice into SMEM as fp16, k-chunked SW128 layout.
    for (int idx = tid; idx < 48 * 64; idx += 512) {
        int row = idx >> 6;          // 0..47
        int c   = idx & 63;          // 8-half chunk within the 512 k-cols
        int kc = c >> 3, c8 = c & 7;
        int g = row >> 4, jl = row & 15;
        const float4* src = (const float4*)
            &Whh[((size_t)(g * H_ + j0 + jl)) * H_ + c * 8];
        uint2 lo = f4h(src[0]);
        uint2 hi = f4h(src[1]);
        uint4 w = make_uint4(lo.x, lo.y, hi.x, hi.y);
        *(uint4*)(smc + WSM_OFF + (kc * 48 + row) * 128 + ((c8 ^ (row & 7)) << 4)) = w;
    }
    __syncthreads();

    float php[4] = {0.f, 0.f, 0.f, 0.f};

    // Prefetch GI for tau = 0.
    float pir[4], piz[4], pinn[4];
    {
        const int rs0 = dir ? (S_ - 1) : 0;
        const size_t gi_base = (size_t)(rs0 * B_) * H3_;
        #pragma unroll
        for (int k = 0; k < 4; k++) {
            size_t girow = gi_base + (size_t)(b0 + rbase + 32 * k) * H3_;
            pir[k]  = GI[girow + jc];
            piz[k]  = GI[girow + H_ + jc];
            pinn[k] = GI[girow + 2 * H_ + jc];
        }
    }

    for (int tau = 0; tau < S_; tau++) {
        const int row_store = dir ? (S_ - 1 - tau) : tau;
        const int row_prev  = dir ? (S_ - tau)     : (tau - 1);

        if (tau > 0) {
            const __half* __restrict__ hh = &Hhd[(size_t)row_prev * B_ * H_];

            float acc[6][4];
            #pragma unroll
            for (int j = 0; j < 6; j++)
                #pragma unroll
                for (int e = 0; e < 4; e++) acc[j][e] = 0.0f;

            auto stageHalf = [&](int half) {
                const int ksel0 = half ? 2 : 0;
                #pragma unroll
                for (int q = 0; q < 8; q++) {
                    int id = tid + q * 512;       // 0..4095
                    int gk = id >> 11;            // which kh group
                    int ii = (id >> 10) & 1;      // chunk within pair
                    int kc = gk * 4 + ksel0 + ii;
                    int r = (id >> 3) & 127, c8 = id & 7;
                    cp16s(sbase + ASM_OFF + kc * 16384 + r * 128
                              + ((c8 ^ (r & 7)) << 4),
                          &hh[(size_t)(b0 + r) * H_ + kc * 64 + c8 * 8]);
                }
                cp_commit();
            };
            stageHalf(0);
            stageHalf(1);

            cp_wait<1>();
            __syncthreads();
            #pragma unroll
            for (int p = 0; p < 2; p++) {
                #pragma unroll
                for (int ii = 0; ii < 2; ii++) {
                    const int i = 2 * p + ii;
                    const int kc = kh * 4 + i;
                    const uint32_t sa = sbase + ASM_OFF + kc * 16384;
                    const uint32_t wb = sbase + WSM_OFF + kc * 48 * 128;
                    #pragma unroll
                    for (int k16 = 0; k16 < 4; k16++) {
                        uint32_t a[4];
                        int rr = wm16 + a_rr;
                        ldsm4(a[0], a[1], a[2], a[3],
                              sa + rr * 128 + (((2 * k16 + a_cs) ^ (rr & 7)) << 4));
                        #pragma unroll
                        for (int g2 = 0; g2 < 3; g2++) {
                            int br = 16 * g2 + b_rr;
                            uint32_t bb0, bb1, bb2, bb3;
                            ldsm4(bb0, bb1, bb2, bb3,
                                  wb + br * 128 + (((2 * k16 + b_cs) ^ (br & 7)) << 4));
                            mma16(acc[2 * g2], a, bb0, bb1);
                            mma16(acc[2 * g2 + 1], a, bb2, bb3);
                        }
                    }
                }
                if (p == 0) { cp_wait<0>(); __syncthreads(); }
            }
            __syncthreads();   // all ASM reads done before GH overlay writes

            const int re = lane >> 2, ce = 2 * (lane & 3);
            #pragma unroll
            for (int j = 0; j < 6; j++) {
                int row = wm16 + re;
                int col = 8 * j + ce;
                int off = kh * 6144 + row * 48 + col;
                *(float2*)&GH[off] = make_float2(acc[j][0], acc[j][1]);
                *(float2*)&GH[off + 8 * 48] = make_float2(acc[j][2], acc[j][3]);
            }
            __syncthreads();
        }

        // Gate epilogue: 128 rows x 16 j, 4 per thread; h kept in registers.
        const size_t h_base = (size_t)(row_store * B_) * H_;
        const int c = tid & 15;
        #pragma unroll
        for (int k = 0; k < 4; k++) {
            int r = rbase + 32 * k;
            int bb = b0 + r;
            float hr_ = 0.f, hz = 0.f, hn = 0.f;
            if (tau > 0) {
                int base = r * 48;
                hr_ = GH[base + c]      + GH[base + 6144 + c];
                hz  = GH[base + 16 + c] + GH[base + 6144 + 16 + c];
                hn  = GH[base + 32 + c] + GH[base + 6144 + 32 + c];
            }
            float rg = 0.5f + 0.5f * tanhax(0.5f * (pir[k] + hr_ + bias_r));
            float zg = 0.5f + 0.5f * tanhax(0.5f * (piz[k] + hz + bias_z));
            float ng = tanhax(pinn[k] + bias_in + rg * (hn + bias_hn));
            float hnew = fmaf(zg, php[k] - ng, ng);
            php[k] = hnew;
            Hhd[h_base + (size_t)bb * H_ + jc] = __float2half_rn(hnew);
        }

        // Split-phase barrier: arrive -> prefetch next GI -> wait.
        if (tau != S_ - 1) {
            __syncthreads();           // all stores issued
            unsigned g = 0, a = 0;
            if (tid == 0) {
                __threadfence();
                g = *bar_gen;
                a = atomicAdd((unsigned*)bar_cnt, 1u);
                if (a == 31) {
                    *bar_cnt = 0;
                    __threadfence();
                    atomicAdd((unsigned*)bar_gen, 1u);
                }
            }
            {
                const int rs1 = dir ? (S_ - 2 - tau) : (tau + 1);
                const size_t gi_base = (size_t)(rs1 * B_) * H3_;
                #pragma unroll
                for (int k = 0; k < 4; k++) {
                    size_t girow = gi_base + (size_t)(b0 + rbase + 32 * k) * H3_;
                    pir[k]  = GI[girow + jc];
                    piz[k]  = GI[girow + H_ + jc];
                    pinn[k] = GI[girow + 2 * H_ + jc];
                }
            }
            if (tid == 0 && a != 31) {
                while (*bar_gen == g) { }
                __threadfence();
            }
            __syncthreads();
        }
    }
}

// ---------------------------------------------------------------------------
extern "C" void kernel_launch(void* const* d_in, const int* in_sizes, int n_in,
                              void* d_out, int out_size) {
    const int*   slot_ids = (const int*)d_in[0];
    const float* value    = (const float*)d_in[1];
    const float* table    = (const float*)d_in[2];
    const float* Wih_f    = (const float*)d_in[3];
    const float* Whh_f    = (const float*)d_in[4];
    const float* bih_f    = (const float*)d_in[5];
    const float* bhh_f    = (const float*)d_in[6];
    const float* Wih_b    = (const float*)d_in[7];
    const float* Whh_b    = (const float*)d_in[8];
    const float* bih_b    = (const float*)d_in[9];
    const float* bhh_b    = (const float*)d_in[10];
    const float* Wproj    = (const float*)d_in[11];
    float* out = (float*)d_out;

    cudaFuncSetAttribute(mm_gemm_kernel<false>,
                         cudaFuncAttributeMaxDynamicSharedMemorySize, GSMEM_BYTES);
    cudaFuncSetAttribute(mm_gemm_kernel<true>,
                         cudaFuncAttributeMaxDynamicSharedMemorySize, GSMEM_BYTES);
    cudaFuncSetAttribute(gru_persistent_kernel,
                         cudaFuncAttributeMaxDynamicSharedMemorySize, PSMEM_BYTES);

    round_weights_kernel<<<(H3_ * DIN_ / 4 + 255) / 256, 256>>>(
        (const float4*)Wih_f, (const float4*)Wih_b, (const float4*)Wproj);
    build_x_kernel<<<M_, 256>>>(slot_ids, value, table);
    mm_gemm_kernel<false><<<dim3(H3_ / 128, M_ / 128, 2), 256, GSMEM_BYTES>>>(nullptr);
    gru_persistent_kernel<<<128, 512, PSMEM_BYTES>>>(
        Whh_f, Whh_b, bih_f, bhh_f, bih_b, bhh_b);
    mm_gemm_kernel<true><<<dim3(E_ / 128, M_ / 128, 1), 256, GSMEM_BYTES>>>(out);
}